// round 9
// baseline (speedup 1.0000x reference)
#include <cuda_runtime.h>
#include <cuda_fp16.h>
#include <cstdint>

#define B_SZ 4096
#define NI   512
#define NO   512
#define KK   (NI*8)          // 4096

// ---------------- scratch (device globals; no allocation allowed) ----------
__device__ __half g_b[(size_t)NO * KK];     //  4 MB  (converted coef)

// ---------------- helpers ---------------------------------------------------
__device__ __forceinline__ uint32_t smem_u32(const void* p) {
    uint32_t a;
    asm("{ .reg .u64 t; cvta.to.shared.u64 t, %1; cvt.u32.u64 %0, t; }"
        : "=r"(a) : "l"(p));
    return a;
}
__device__ __forceinline__ void cp16(uint32_t dst, const void* src) {
    asm volatile("cp.async.cg.shared.global [%0], [%1], 16;"
                 :: "r"(dst), "l"(src));
}
__device__ __forceinline__ void ldsm4(uint32_t* r, uint32_t addr) {
    asm volatile("ldmatrix.sync.aligned.m8n8.x4.shared.b16 {%0,%1,%2,%3}, [%4];"
                 : "=r"(r[0]), "=r"(r[1]), "=r"(r[2]), "=r"(r[3]) : "r"(addr));
}
__device__ __forceinline__ void sts128(uint32_t addr, const void* v) {
    const uint32_t* u = (const uint32_t*)v;
    asm volatile("st.shared.v4.b32 [%0], {%1,%2,%3,%4};"
                 :: "r"(addr), "r"(u[0]), "r"(u[1]), "r"(u[2]), "r"(u[3]));
}
__device__ __forceinline__ void mma16816(float* d, const uint32_t* a,
                                         uint32_t b0, uint32_t b1) {
    asm volatile(
        "mma.sync.aligned.m16n8k16.row.col.f32.f16.f16.f32 "
        "{%0,%1,%2,%3}, {%4,%5,%6,%7}, {%8,%9}, {%0,%1,%2,%3};"
        : "+f"(d[0]), "+f"(d[1]), "+f"(d[2]), "+f"(d[3])
        : "r"(a[0]), "r"(a[1]), "r"(a[2]), "r"(a[3]), "r"(b0), "r"(b1));
}

// fast tanh: rel err ~1e-6, far below fp16 quantization (2^-11)
__device__ __forceinline__ float fast_tanh(float x) {
    float xc = fminf(fmaxf(x, -9.0f), 9.0f);
    float e  = __expf(2.0f * xc);
    return 1.0f - __fdividef(2.0f, e + 1.0f);
}

__device__ __forceinline__ void jacobi8_to_half(float t, __half* h) {
    float p[8];
    p[0] = 1.0f;
    p[1] = 2.0f * t;
    p[2] = 1.875f      * t * p[1] - 0.75f       * p[0];
    p[3] = 1.8666667f  * t * p[2] - 0.8f        * p[1];
    p[4] = 1.875f      * t * p[3] - 0.8333333f  * p[2];
    p[5] = 1.8857143f  * t * p[4] - 0.85714287f * p[3];
    p[6] = 1.8958334f  * t * p[5] - 0.875f      * p[4];
    p[7] = 1.9047619f  * t * p[6] - 0.8888889f  * p[5];
    #pragma unroll
    for (int d = 0; d < 8; ++d) h[d] = __float2half_rn(p[d]);
}

// ---------------- phase 1: coef convert only --------------------------------
__global__ __launch_bounds__(256) void coef_convert(const float* __restrict__ coef) {
    int base = blockIdx.x * 1024 + threadIdx.x;
    #pragma unroll
    for (int e = 0; e < 4; ++e) {
        int idx = base + e * 256;
        float p[8];
        const float4* s = reinterpret_cast<const float4*>(coef + (size_t)idx * 8);
        *reinterpret_cast<float4*>(p)     = s[0];
        *reinterpret_cast<float4*>(p + 4) = s[1];
        __half h[8];
        #pragma unroll
        for (int d = 0; d < 8; ++d) h[d] = __float2half_rn(p[d]);
        *reinterpret_cast<uint4*>(g_b + (size_t)idx * 8) =
            *reinterpret_cast<uint4*>(h);
    }
}

// ---------------- phase 2: fused expand + fp16 warp-MMA GEMM ----------------
// out[4096,512] = Jac(x)[4096,4096] @ B[512,4096]^T, fp32 accumulate.
// BM=BN=128, BK=128 (= 16 input cols x 8 orders). 3 stages.
// A stage is PRODUCED in-kernel (tanh + Jacobi recurrence -> STS), one
// iteration ahead; B stage loaded via cp.async, two iterations ahead.
#define BKH 128
#define SUB_BYTES 16384
#define STAGE_BYTES 65536     // A(32KB) + B(32KB)
#define NSTAGE 3
#define SMEM_DYN (1024 + NSTAGE * STAGE_BYTES)

// swizzled offset inside a [rows][64 fp16] subtile: 128B rows, 16B chunks
__device__ __forceinline__ uint32_t swoff(int row, int chunk) {
    return (uint32_t)(row * 128 + ((chunk ^ (row & 7)) * 16));
}

// load one 128-row x 64-fp16 B subtile (16KB) with cp.async
__device__ __forceinline__ void load_sub(uint32_t sdst,
                                         const __half* gsrc, int tid) {
    #pragma unroll
    for (int t = 0; t < 4; ++t) {
        int idx = t * 256 + tid;           // 1024 chunks of 16B
        int row = idx >> 3, ch = idx & 7;
        cp16(sdst + swoff(row, ch),
             (const char*)(gsrc + (size_t)row * KK) + ch * 16);
    }
}
__device__ __forceinline__ void load_b_stage(uint32_t sb, const __half* B,
                                             int k0, int tid) {
    load_sub(sb,             B + k0,      tid);
    load_sub(sb + SUB_BYTES, B + k0 + 64, tid);
}

// produce A stage: 128 rows x 16 input columns -> jacobi fp16, swizzled STS.
// thread -> (icol = tid&15, rowgroup = tid>>4); 8 rows per thread (stride 16).
// One chain's 8 orders = K positions [icol*8, icol*8+8) = one 16B chunk.
__device__ __forceinline__ void produce_a(uint32_t asb,
                                          const float* __restrict__ xstrip,
                                          int icol0, int tid) {
    const int icl = tid & 15;
    const int rg  = tid >> 4;
    const uint32_t sub = asb + (uint32_t)(icl >> 3) * SUB_BYTES;
    const int c = icl & 7;
    const float* xp = xstrip + icol0 + icl;
    #pragma unroll
    for (int e = 0; e < 8; ++e) {
        int row = rg + e * 16;
        float t = fast_tanh(xp[(size_t)row * NI]);
        __half h[8];
        jacobi8_to_half(t, h);
        sts128(sub + swoff(row, c), h);
    }
}

__global__ __launch_bounds__(256, 1)
void kan_gemm(const float* __restrict__ x, float* __restrict__ out) {
    extern __shared__ char smraw[];
    uint32_t sbase = (smem_u32(smraw) + 1023) & ~1023u;

    const int tid  = threadIdx.x;
    const int lane = tid & 31;
    const int wid  = tid >> 5;
    const int wm   = wid >> 1;          // 0..3  (32-row slice)
    const int wn   = wid & 1;           // 0..1  (64-col slice)
    const int brow = blockIdx.y * 128;
    const int bcol = blockIdx.x * 128;

    const float*  X = x   + (size_t)brow * NI;
    const __half* B = g_b + (size_t)bcol * KK;

    float acc[2][8][4];
    #pragma unroll
    for (int i = 0; i < 2; ++i)
        #pragma unroll
        for (int j = 0; j < 8; ++j)
            #pragma unroll
            for (int c = 0; c < 4; ++c) acc[i][j][c] = 0.0f;

    // ldmatrix per-lane row / chunk-half mapping
    const int ar  = lane & 15;                        // A row within m16 tile
    const int ac  = lane >> 4;                        // A k-chunk half (0/1)
    const int br0 = ((lane >> 4) << 3) + (lane & 7);  // B row within n16 pair
    const int bc  = (lane >> 3) & 1;                  // B k-chunk half (0/1)

    // prologue: B stages 0,1 via cp.async; A stage 0 produced in-register
    #pragma unroll
    for (int t = 0; t < NSTAGE - 1; ++t) {
        load_b_stage(sbase + t * STAGE_BYTES + 2 * SUB_BYTES, B, t * BKH, tid);
        asm volatile("cp.async.commit_group;" ::: "memory");
    }
    produce_a(sbase, X, 0, tid);

    const int NIT = KK / BKH;            // 32
    for (int kt = 0; kt < NIT; ++kt) {
        asm volatile("cp.async.wait_group %0;" :: "n"(NSTAGE - 2) : "memory");
        __syncthreads();   // B(kt) ready; A(kt) STS visible; stage slots free

        // prefetch B(kt+2)
        int nk = kt + NSTAGE - 1;
        if (nk < NIT) {
            load_b_stage(sbase + (nk % NSTAGE) * STAGE_BYTES + 2 * SUB_BYTES,
                         B, nk * BKH, tid);
        }
        asm volatile("cp.async.commit_group;" ::: "memory");

        // produce A(kt+1) while tensor pipe chews on A(kt)/B(kt)
        if (kt + 1 < NIT) {
            produce_a(sbase + ((kt + 1) % NSTAGE) * STAGE_BYTES,
                      X, (kt + 1) * 16, tid);
        }

        // compute from stage kt%3: two 64-col k-halves x 4 k16-steps
        uint32_t sb = sbase + (kt % NSTAGE) * STAGE_BYTES;
        #pragma unroll
        for (int h = 0; h < 2; ++h) {
            uint32_t aB = sb + h * SUB_BYTES;
            uint32_t bB = sb + (2 + h) * SUB_BYTES;
            #pragma unroll
            for (int s = 0; s < 4; ++s) {
                uint32_t a[2][4];
                #pragma unroll
                for (int mt = 0; mt < 2; ++mt)
                    ldsm4(a[mt], aB + swoff(wm * 32 + mt * 16 + ar, s * 2 + ac));
                uint32_t b[4][4];
                #pragma unroll
                for (int p = 0; p < 4; ++p)
                    ldsm4(b[p], bB + swoff(wn * 64 + p * 16 + br0, s * 2 + bc));
                #pragma unroll
                for (int mt = 0; mt < 2; ++mt)
                    #pragma unroll
                    for (int p = 0; p < 4; ++p) {
                        mma16816(acc[mt][2*p],   a[mt], b[p][0], b[p][1]);
                        mma16816(acc[mt][2*p+1], a[mt], b[p][2], b[p][3]);
                    }
            }
        }
        __syncthreads();
    }

    // epilogue: c-fragment layout -> float2 stores
    const int r0 = brow + wm * 32 + (lane >> 2);
    const int c0 = bcol + wn * 64 + (lane & 3) * 2;
    #pragma unroll
    for (int mt = 0; mt < 2; ++mt) {
        #pragma unroll
        for (int nt = 0; nt < 8; ++nt) {
            float* p = out + (size_t)(r0 + mt * 16) * NO + c0 + nt * 8;
            *reinterpret_cast<float2*>(p) =
                make_float2(acc[mt][nt][0], acc[mt][nt][1]);
            *reinterpret_cast<float2*>(p + 8 * NO) =
                make_float2(acc[mt][nt][2], acc[mt][nt][3]);
        }
    }
}

// ---------------- launcher ---------------------------------------------------
extern "C" void kernel_launch(void* const* d_in, const int* in_sizes, int n_in,
                              void* d_out, int out_size)
{
    const float* x    = (const float*)d_in[0];   // [4096, 512]
    const float* coef = (const float*)d_in[1];   // [512, 512, 8]
    float* out        = (float*)d_out;           // [4096, 512]

    cudaFuncSetAttribute(kan_gemm, cudaFuncAttributeMaxDynamicSharedMemorySize,
                         SMEM_DYN);

    coef_convert<<<(NO * NI) / 1024, 256>>>(coef);

    dim3 grid(NO / 128, B_SZ / 128);             // (4, 32)
    kan_gemm<<<grid, 256, SMEM_DYN>>>(x, out);
}

// round 10
// speedup vs baseline: 1.0038x; 1.0038x over previous
#include <cuda_runtime.h>
#include <cuda_fp16.h>
#include <cstdint>

#define B_SZ 4096
#define NI   512
#define NO   512
#define KK   (NI*8)          // 4096

// ---------------- scratch (device globals; no allocation allowed) ----------
__device__ __half g_b[(size_t)NO * KK];     //  4 MB  (converted coef)

// ---------------- helpers ---------------------------------------------------
__device__ __forceinline__ uint32_t smem_u32(const void* p) {
    uint32_t a;
    asm("{ .reg .u64 t; cvta.to.shared.u64 t, %1; cvt.u32.u64 %0, t; }"
        : "=r"(a) : "l"(p));
    return a;
}
__device__ __forceinline__ void cp16(uint32_t dst, const void* src) {
    asm volatile("cp.async.cg.shared.global [%0], [%1], 16;"
                 :: "r"(dst), "l"(src));
}
__device__ __forceinline__ void ldsm4(uint32_t* r, uint32_t addr) {
    asm volatile("ldmatrix.sync.aligned.m8n8.x4.shared.b16 {%0,%1,%2,%3}, [%4];"
                 : "=r"(r[0]), "=r"(r[1]), "=r"(r[2]), "=r"(r[3]) : "r"(addr));
}
__device__ __forceinline__ void sts128(uint32_t addr, const uint32_t* u) {
    asm volatile("st.shared.v4.b32 [%0], {%1,%2,%3,%4};"
                 :: "r"(addr), "r"(u[0]), "r"(u[1]), "r"(u[2]), "r"(u[3]));
}
__device__ __forceinline__ void mma16816(float* d, const uint32_t* a,
                                         uint32_t b0, uint32_t b1) {
    asm volatile(
        "mma.sync.aligned.m16n8k16.row.col.f32.f16.f16.f32 "
        "{%0,%1,%2,%3}, {%4,%5,%6,%7}, {%8,%9}, {%0,%1,%2,%3};"
        : "+f"(d[0]), "+f"(d[1]), "+f"(d[2]), "+f"(d[3])
        : "r"(a[0]), "r"(a[1]), "r"(a[2]), "r"(a[3]), "r"(b0), "r"(b1));
}

// fast tanh: rel err ~1e-6, far below fp16 quantization (2^-11)
__device__ __forceinline__ float fast_tanh(float x) {
    float xc = fminf(fmaxf(x, -9.0f), 9.0f);
    float e  = __expf(2.0f * xc);
    return 1.0f - __fdividef(2.0f, e + 1.0f);
}

__device__ __forceinline__ uint32_t packh2(float lo, float hi) {
    __half2 h = __float22half2_rn(make_float2(lo, hi));
    return *reinterpret_cast<uint32_t*>(&h);
}

// ---------------- phase 1: coef convert only --------------------------------
__global__ __launch_bounds__(256) void coef_convert(const float* __restrict__ coef) {
    int base = blockIdx.x * 1024 + threadIdx.x;
    #pragma unroll
    for (int e = 0; e < 4; ++e) {
        int idx = base + e * 256;
        float p[8];
        const float4* s = reinterpret_cast<const float4*>(coef + (size_t)idx * 8);
        *reinterpret_cast<float4*>(p)     = s[0];
        *reinterpret_cast<float4*>(p + 4) = s[1];
        __half h[8];
        #pragma unroll
        for (int d = 0; d < 8; ++d) h[d] = __float2half_rn(p[d]);
        *reinterpret_cast<uint4*>(g_b + (size_t)idx * 8) =
            *reinterpret_cast<uint4*>(h);
    }
}

// ---------------- phase 2: fused expand + fp16 warp-MMA GEMM ----------------
// out[4096,512] = Jac(x)[4096,4096] @ B[512,4096]^T, fp32 accumulate.
// BM=BN=128, BK=128 (= 16 input cols x 8 orders). 3 stages.
// A stage PRODUCED in-kernel (ILP-restructured: 4 independent chains in
// lockstep), one iteration ahead; B via cp.async, two ahead.
#define BKH 128
#define SUB_BYTES 16384
#define STAGE_BYTES 65536     // A(32KB) + B(32KB)
#define NSTAGE 3
#define SMEM_DYN (1024 + NSTAGE * STAGE_BYTES)

// swizzled offset inside a [rows][64 fp16] subtile: 128B rows, 16B chunks
__device__ __forceinline__ uint32_t swoff(int row, int chunk) {
    return (uint32_t)(row * 128 + ((chunk ^ (row & 7)) * 16));
}

// load one 128-row x 64-fp16 B subtile (16KB) with cp.async
__device__ __forceinline__ void load_sub(uint32_t sdst,
                                         const __half* gsrc, int tid) {
    #pragma unroll
    for (int t = 0; t < 4; ++t) {
        int idx = t * 256 + tid;           // 1024 chunks of 16B
        int row = idx >> 3, ch = idx & 7;
        cp16(sdst + swoff(row, ch),
             (const char*)(gsrc + (size_t)row * KK) + ch * 16);
    }
}
__device__ __forceinline__ void load_b_stage(uint32_t sb, const __half* B,
                                             int k0, int tid) {
    load_sub(sb,             B + k0,      tid);
    load_sub(sb + SUB_BYTES, B + k0 + 64, tid);
}

// produce A stage: 128 rows x 16 input cols -> jacobi fp16, swizzled STS.
// thread -> (icol = tid&15, rowgroup = tid>>4); 8 rows per thread (stride 16),
// processed as 2 groups of 4 INDEPENDENT chains run in lockstep (ILP=4):
// batched loads -> batched tanh -> interleaved recurrence -> packed STS.
__device__ __forceinline__ void produce_a(uint32_t asb,
                                          const float* __restrict__ xstrip,
                                          int icol0, int tid) {
    const int icl = tid & 15;
    const int rg  = tid >> 4;
    const uint32_t sub = asb + (uint32_t)(icl >> 3) * SUB_BYTES;
    const int c = icl & 7;
    const float* xp = xstrip + icol0 + icl;

    #pragma unroll
    for (int g = 0; g < 2; ++g) {
        float xv[4];
        #pragma unroll
        for (int e = 0; e < 4; ++e)
            xv[e] = xp[(size_t)(rg + (g * 4 + e) * 16) * NI];
        float t[4];
        #pragma unroll
        for (int e = 0; e < 4; ++e) t[e] = fast_tanh(xv[e]);

        uint32_t outv[4][4];
        float pa[4], pb[4];
        #pragma unroll
        for (int e = 0; e < 4; ++e) {
            pa[e] = 1.0f;
            pb[e] = 2.0f * t[e];
            outv[e][0] = packh2(1.0f, pb[e]);
        }
        const float K1[6] = {1.875f, 1.8666667f, 1.875f,
                             1.8857143f, 1.8958334f, 1.9047619f};
        const float K3[6] = {0.75f, 0.8f, 0.8333333f,
                             0.85714287f, 0.875f, 0.8888889f};
        #pragma unroll
        for (int j = 0; j < 3; ++j) {
            #pragma unroll
            for (int e = 0; e < 4; ++e) {
                float pe = K1[2*j]   * t[e] * pb[e] - K3[2*j]   * pa[e];
                float po = K1[2*j+1] * t[e] * pe    - K3[2*j+1] * pb[e];
                pa[e] = pe; pb[e] = po;
                outv[e][j + 1] = packh2(pe, po);
            }
        }
        #pragma unroll
        for (int e = 0; e < 4; ++e)
            sts128(sub + swoff(rg + (g * 4 + e) * 16, c), outv[e]);
    }
}

__global__ __launch_bounds__(256, 1)
void kan_gemm(const float* __restrict__ x, float* __restrict__ out) {
    extern __shared__ char smraw[];
    uint32_t sbase = (smem_u32(smraw) + 1023) & ~1023u;

    const int tid  = threadIdx.x;
    const int lane = tid & 31;
    const int wid  = tid >> 5;
    const int wm   = wid >> 1;          // 0..3  (32-row slice)
    const int wn   = wid & 1;           // 0..1  (64-col slice)
    const int brow = blockIdx.y * 128;
    const int bcol = blockIdx.x * 128;

    const float*  X = x   + (size_t)brow * NI;
    const __half* B = g_b + (size_t)bcol * KK;

    float acc[2][8][4];
    #pragma unroll
    for (int i = 0; i < 2; ++i)
        #pragma unroll
        for (int j = 0; j < 8; ++j)
            #pragma unroll
            for (int c = 0; c < 4; ++c) acc[i][j][c] = 0.0f;

    // ldmatrix per-lane row / chunk-half mapping
    const int ar  = lane & 15;                        // A row within m16 tile
    const int ac  = lane >> 4;                        // A k-chunk half (0/1)
    const int br0 = ((lane >> 4) << 3) + (lane & 7);  // B row within n16 pair
    const int bc  = (lane >> 3) & 1;                  // B k-chunk half (0/1)

    // prologue: B stages 0,1 via cp.async; A stage 0 produced in-kernel
    #pragma unroll
    for (int t = 0; t < NSTAGE - 1; ++t) {
        load_b_stage(sbase + t * STAGE_BYTES + 2 * SUB_BYTES, B, t * BKH, tid);
        asm volatile("cp.async.commit_group;" ::: "memory");
    }
    produce_a(sbase, X, 0, tid);

    const int NIT = KK / BKH;            // 32
    for (int kt = 0; kt < NIT; ++kt) {
        asm volatile("cp.async.wait_group %0;" :: "n"(NSTAGE - 2) : "memory");
        __syncthreads();   // B(kt) ready; A(kt) STS visible; stage slots free

        // prefetch B(kt+2)
        int nk = kt + NSTAGE - 1;
        if (nk < NIT) {
            load_b_stage(sbase + (nk % NSTAGE) * STAGE_BYTES + 2 * SUB_BYTES,
                         B, nk * BKH, tid);
        }
        asm volatile("cp.async.commit_group;" ::: "memory");

        // produce A(kt+1) while tensor pipe chews on A(kt)/B(kt)
        if (kt + 1 < NIT) {
            produce_a(sbase + ((kt + 1) % NSTAGE) * STAGE_BYTES,
                      X, (kt + 1) * 16, tid);
        }

        // compute from stage kt%3: two 64-col k-halves x 4 k16-steps
        uint32_t sb = sbase + (kt % NSTAGE) * STAGE_BYTES;
        #pragma unroll
        for (int h = 0; h < 2; ++h) {
            uint32_t aB = sb + h * SUB_BYTES;
            uint32_t bB = sb + (2 + h) * SUB_BYTES;
            #pragma unroll
            for (int s = 0; s < 4; ++s) {
                uint32_t a[2][4];
                #pragma unroll
                for (int mt = 0; mt < 2; ++mt)
                    ldsm4(a[mt], aB + swoff(wm * 32 + mt * 16 + ar, s * 2 + ac));
                uint32_t b[4][4];
                #pragma unroll
                for (int p = 0; p < 4; ++p)
                    ldsm4(b[p], bB + swoff(wn * 64 + p * 16 + br0, s * 2 + bc));
                #pragma unroll
                for (int mt = 0; mt < 2; ++mt)
                    #pragma unroll
                    for (int p = 0; p < 4; ++p) {
                        mma16816(acc[mt][2*p],   a[mt], b[p][0], b[p][1]);
                        mma16816(acc[mt][2*p+1], a[mt], b[p][2], b[p][3]);
                    }
            }
        }
        __syncthreads();
    }

    // epilogue: c-fragment layout -> float2 stores
    const int r0 = brow + wm * 32 + (lane >> 2);
    const int c0 = bcol + wn * 64 + (lane & 3) * 2;
    #pragma unroll
    for (int mt = 0; mt < 2; ++mt) {
        #pragma unroll
        for (int nt = 0; nt < 8; ++nt) {
            float* p = out + (size_t)(r0 + mt * 16) * NO + c0 + nt * 8;
            *reinterpret_cast<float2*>(p) =
                make_float2(acc[mt][nt][0], acc[mt][nt][1]);
            *reinterpret_cast<float2*>(p + 8 * NO) =
                make_float2(acc[mt][nt][2], acc[mt][nt][3]);
        }
    }
}

// ---------------- launcher ---------------------------------------------------
extern "C" void kernel_launch(void* const* d_in, const int* in_sizes, int n_in,
                              void* d_out, int out_size)
{
    const float* x    = (const float*)d_in[0];   // [4096, 512]
    const float* coef = (const float*)d_in[1];   // [512, 512, 8]
    float* out        = (float*)d_out;           // [4096, 512]

    cudaFuncSetAttribute(kan_gemm, cudaFuncAttributeMaxDynamicSharedMemorySize,
                         SMEM_DYN);

    coef_convert<<<(NO * NI) / 1024, 256>>>(coef);

    dim3 grid(NO / 128, B_SZ / 128);             // (4, 32)
    kan_gemm<<<grid, 256, SMEM_DYN>>>(x, out);
}

// round 11
// speedup vs baseline: 1.1507x; 1.1463x over previous
#include <cuda_runtime.h>
#include <cuda_fp16.h>
#include <cstdint>

#define B_SZ 4096
#define NI   512
#define NO   512
#define KK   (NI*8)          // 4096

// ---------------- scratch (device globals; no allocation allowed) ----------
__device__ __half g_a[(size_t)B_SZ * KK];   // 32 MB
__device__ __half g_b[(size_t)NO * KK];     //  4 MB

// ---------------- helpers ---------------------------------------------------
__device__ __forceinline__ uint32_t smem_u32(const void* p) {
    uint32_t a;
    asm("{ .reg .u64 t; cvta.to.shared.u64 t, %1; cvt.u32.u64 %0, t; }"
        : "=r"(a) : "l"(p));
    return a;
}
__device__ __forceinline__ void cp16(uint32_t dst, const void* src) {
    asm volatile("cp.async.cg.shared.global [%0], [%1], 16;"
                 :: "r"(dst), "l"(src));
}
__device__ __forceinline__ void ldsm4(uint32_t* r, uint32_t addr) {
    asm volatile("ldmatrix.sync.aligned.m8n8.x4.shared.b16 {%0,%1,%2,%3}, [%4];"
                 : "=r"(r[0]), "=r"(r[1]), "=r"(r[2]), "=r"(r[3]) : "r"(addr));
}
__device__ __forceinline__ void mma16816(float* d, const uint32_t* a,
                                         uint32_t b0, uint32_t b1) {
    asm volatile(
        "mma.sync.aligned.m16n8k16.row.col.f32.f16.f16.f32 "
        "{%0,%1,%2,%3}, {%4,%5,%6,%7}, {%8,%9}, {%0,%1,%2,%3};"
        : "+f"(d[0]), "+f"(d[1]), "+f"(d[2]), "+f"(d[3])
        : "r"(a[0]), "r"(a[1]), "r"(a[2]), "r"(a[3]), "r"(b0), "r"(b1));
}

// fast tanh: rel err ~1e-6, far below fp16 quantization (2^-11)
__device__ __forceinline__ float fast_tanh(float x) {
    float xc = fminf(fmaxf(x, -9.0f), 9.0f);
    float e  = __expf(2.0f * xc);
    return 1.0f - __fdividef(2.0f, e + 1.0f);
}

__device__ __forceinline__ void jacobi8_to_half(float t, __half* h) {
    float p[8];
    p[0] = 1.0f;
    p[1] = 2.0f * t;
    p[2] = 1.875f      * t * p[1] - 0.75f       * p[0];
    p[3] = 1.8666667f  * t * p[2] - 0.8f        * p[1];
    p[4] = 1.875f      * t * p[3] - 0.8333333f  * p[2];
    p[5] = 1.8857143f  * t * p[4] - 0.85714287f * p[3];
    p[6] = 1.8958334f  * t * p[5] - 0.875f      * p[4];
    p[7] = 1.9047619f  * t * p[6] - 0.8888889f  * p[5];
    #pragma unroll
    for (int d = 0; d < 8; ++d) h[d] = __float2half_rn(p[d]);
}

// ---------------- phase 1: jacobi expansion + coef convert ------------------
// 4 elems/thread, stride-256 groups: coalesced loads AND stores
__global__ __launch_bounds__(256) void jacobi_expand(const float* __restrict__ x) {
    int base = blockIdx.x * 1024 + threadIdx.x;
    float t[4];
    #pragma unroll
    for (int e = 0; e < 4; ++e) t[e] = fast_tanh(x[base + e * 256]);
    #pragma unroll
    for (int e = 0; e < 4; ++e) {
        __half h[8];
        jacobi8_to_half(t[e], h);
        *reinterpret_cast<uint4*>(g_a + (size_t)(base + e * 256) * 8) =
            *reinterpret_cast<uint4*>(h);
    }
}

__global__ __launch_bounds__(256) void coef_convert(const float* __restrict__ coef) {
    int base = blockIdx.x * 1024 + threadIdx.x;
    #pragma unroll
    for (int e = 0; e < 4; ++e) {
        int idx = base + e * 256;
        float p[8];
        const float4* s = reinterpret_cast<const float4*>(coef + (size_t)idx * 8);
        *reinterpret_cast<float4*>(p)     = s[0];
        *reinterpret_cast<float4*>(p + 4) = s[1];
        __half h[8];
        #pragma unroll
        for (int d = 0; d < 8; ++d) h[d] = __float2half_rn(p[d]);
        *reinterpret_cast<uint4*>(g_b + (size_t)idx * 8) =
            *reinterpret_cast<uint4*>(h);
    }
}

// ---------------- phase 2: fp16 warp-MMA GEMM, 2 CTAs/SM --------------------
// out[4096,512] = A[4096,4096] @ B[512,4096]^T, fp32 accumulate.
// BM=BN=128, BK=64. Stage = A(16KB)+B(16KB) = 32KB. 3 stages = 96KB/CTA,
// so TWO CTAs co-reside per SM (4 warps/SMSP) to hide latency.
#define BKH 64
#define STAGE_BYTES 32768
#define NSTAGE 3
#define SMEM_DYN (1024 + NSTAGE * STAGE_BYTES)

// swizzled offset inside a [rows][64 fp16] tile: 128B rows, 16B chunks
__device__ __forceinline__ uint32_t swoff(int row, int chunk) {
    return (uint32_t)(row * 128 + ((chunk ^ (row & 7)) * 16));
}

// load one 128-row x 64-fp16 tile (16KB) with cp.async
__device__ __forceinline__ void load_tile(uint32_t sdst,
                                          const __half* gsrc, int tid) {
    #pragma unroll
    for (int t = 0; t < 4; ++t) {
        int idx = t * 256 + tid;           // 1024 chunks of 16B
        int row = idx >> 3, ch = idx & 7;
        cp16(sdst + swoff(row, ch),
             (const char*)(gsrc + (size_t)row * KK) + ch * 16);
    }
}

__global__ __launch_bounds__(256, 2)
void kan_gemm(float* __restrict__ out) {
    extern __shared__ char smraw[];
    uint32_t sbase = (smem_u32(smraw) + 1023) & ~1023u;

    const int tid  = threadIdx.x;
    const int lane = tid & 31;
    const int wid  = tid >> 5;
    const int wm   = wid >> 1;          // 0..3  (32-row slice)
    const int wn   = wid & 1;           // 0..1  (64-col slice)
    const int brow = blockIdx.y * 128;
    const int bcol = blockIdx.x * 128;

    const __half* A = g_a + (size_t)brow * KK;
    const __half* B = g_b + (size_t)bcol * KK;

    float acc[2][8][4];
    #pragma unroll
    for (int i = 0; i < 2; ++i)
        #pragma unroll
        for (int j = 0; j < 8; ++j)
            #pragma unroll
            for (int c = 0; c < 4; ++c) acc[i][j][c] = 0.0f;

    // ldmatrix per-lane row / chunk-half mapping
    const int ar  = lane & 15;                        // A row within m16 tile
    const int ac  = lane >> 4;                        // A k-chunk half (0/1)
    const int br0 = ((lane >> 4) << 3) + (lane & 7);  // B row within n16 pair
    const int bc  = (lane >> 3) & 1;                  // B k-chunk half (0/1)

    // prologue: stages 0,1
    #pragma unroll
    for (int t = 0; t < NSTAGE - 1; ++t) {
        uint32_t sb = sbase + t * STAGE_BYTES;
        int k0 = t * BKH;
        load_tile(sb,         A + k0, tid);
        load_tile(sb + 16384, B + k0, tid);
        asm volatile("cp.async.commit_group;" ::: "memory");
    }

    const int NIT = KK / BKH;            // 64
    for (int kt = 0; kt < NIT; ++kt) {
        asm volatile("cp.async.wait_group %0;" :: "n"(NSTAGE - 2) : "memory");
        __syncthreads();

        // prefetch tile kt+2 into stage (kt+2)%3
        int nk = kt + NSTAGE - 1;
        if (nk < NIT) {
            uint32_t sb = sbase + (nk % NSTAGE) * STAGE_BYTES;
            int k0 = nk * BKH;
            load_tile(sb,         A + k0, tid);
            load_tile(sb + 16384, B + k0, tid);
        }
        asm volatile("cp.async.commit_group;" ::: "memory");

        // compute from stage kt%3
        uint32_t sb = sbase + (kt % NSTAGE) * STAGE_BYTES;
        uint32_t aB = sb, bB = sb + 16384;

        #pragma unroll
        for (int s = 0; s < 4; ++s) {            // 4 k16 steps in BK=64
            uint32_t a[2][4];
            #pragma unroll
            for (int mt = 0; mt < 2; ++mt)
                ldsm4(a[mt], aB + swoff(wm * 32 + mt * 16 + ar, s * 2 + ac));
            uint32_t b[4][4];
            #pragma unroll
            for (int p = 0; p < 4; ++p)
                ldsm4(b[p], bB + swoff(wn * 64 + p * 16 + br0, s * 2 + bc));
            #pragma unroll
            for (int mt = 0; mt < 2; ++mt)
                #pragma unroll
                for (int p = 0; p < 4; ++p) {
                    mma16816(acc[mt][2*p],   a[mt], b[p][0], b[p][1]);
                    mma16816(acc[mt][2*p+1], a[mt], b[p][2], b[p][3]);
                }
        }
        __syncthreads();
    }

    // epilogue: c-fragment layout -> float2 stores
    const int r0 = brow + wm * 32 + (lane >> 2);
    const int c0 = bcol + wn * 64 + (lane & 3) * 2;
    #pragma unroll
    for (int mt = 0; mt < 2; ++mt) {
        #pragma unroll
        for (int nt = 0; nt < 8; ++nt) {
            float* p = out + (size_t)(r0 + mt * 16) * NO + c0 + nt * 8;
            *reinterpret_cast<float2*>(p) =
                make_float2(acc[mt][nt][0], acc[mt][nt][1]);
            *reinterpret_cast<float2*>(p + 8 * NO) =
                make_float2(acc[mt][nt][2], acc[mt][nt][3]);
        }
    }
}

// ---------------- launcher ---------------------------------------------------
extern "C" void kernel_launch(void* const* d_in, const int* in_sizes, int n_in,
                              void* d_out, int out_size)
{
    const float* x    = (const float*)d_in[0];   // [4096, 512]
    const float* coef = (const float*)d_in[1];   // [512, 512, 8]
    float* out        = (float*)d_out;           // [4096, 512]

    cudaFuncSetAttribute(kan_gemm, cudaFuncAttributeMaxDynamicSharedMemorySize,
                         SMEM_DYN);

    jacobi_expand<<<(B_SZ * NI) / 1024, 256>>>(x);
    coef_convert<<<(NO * NI) / 1024, 256>>>(coef);

    dim3 grid(NO / 128, B_SZ / 128);             // (4, 32)
    kan_gemm<<<grid, 256, SMEM_DYN>>>(out);
}

// round 12
// speedup vs baseline: 1.1551x; 1.0039x over previous
#include <cuda_runtime.h>
#include <cuda_fp16.h>
#include <cstdint>

#define B_SZ 4096
#define NI   512
#define NO   512
#define KK   (NI*8)          // 4096

// ---------------- scratch (device globals; no allocation allowed) ----------
__device__ __half g_a[(size_t)B_SZ * KK];   // 32 MB
__device__ __half g_b[(size_t)NO * KK];     //  4 MB

// ---------------- helpers ---------------------------------------------------
__device__ __forceinline__ uint32_t smem_u32(const void* p) {
    uint32_t a;
    asm("{ .reg .u64 t; cvta.to.shared.u64 t, %1; cvt.u32.u64 %0, t; }"
        : "=r"(a) : "l"(p));
    return a;
}
__device__ __forceinline__ void cp16(uint32_t dst, const void* src) {
    asm volatile("cp.async.cg.shared.global [%0], [%1], 16;"
                 :: "r"(dst), "l"(src));
}
__device__ __forceinline__ void ldsm4(uint32_t* r, uint32_t addr) {
    asm volatile("ldmatrix.sync.aligned.m8n8.x4.shared.b16 {%0,%1,%2,%3}, [%4];"
                 : "=r"(r[0]), "=r"(r[1]), "=r"(r[2]), "=r"(r[3]) : "r"(addr));
}
__device__ __forceinline__ void mma16816(float* d, const uint32_t* a,
                                         uint32_t b0, uint32_t b1) {
    asm volatile(
        "mma.sync.aligned.m16n8k16.row.col.f32.f16.f16.f32 "
        "{%0,%1,%2,%3}, {%4,%5,%6,%7}, {%8,%9}, {%0,%1,%2,%3};"
        : "+f"(d[0]), "+f"(d[1]), "+f"(d[2]), "+f"(d[3])
        : "r"(a[0]), "r"(a[1]), "r"(a[2]), "r"(a[3]), "r"(b0), "r"(b1));
}

// fast tanh: rel err ~1e-6, far below fp16 quantization (2^-11)
__device__ __forceinline__ float fast_tanh(float x) {
    float xc = fminf(fmaxf(x, -9.0f), 9.0f);
    float e  = __expf(2.0f * xc);
    return 1.0f - __fdividef(2.0f, e + 1.0f);
}

__device__ __forceinline__ void jacobi8_to_half(float t, __half* h) {
    float p[8];
    p[0] = 1.0f;
    p[1] = 2.0f * t;
    p[2] = 1.875f      * t * p[1] - 0.75f       * p[0];
    p[3] = 1.8666667f  * t * p[2] - 0.8f        * p[1];
    p[4] = 1.875f      * t * p[3] - 0.8333333f  * p[2];
    p[5] = 1.8857143f  * t * p[4] - 0.85714287f * p[3];
    p[6] = 1.8958334f  * t * p[5] - 0.875f      * p[4];
    p[7] = 1.9047619f  * t * p[6] - 0.8888889f  * p[5];
    #pragma unroll
    for (int d = 0; d < 8; ++d) h[d] = __float2half_rn(p[d]);
}

// ---------------- phase 1: jacobi expansion + coef convert ------------------
__global__ __launch_bounds__(256) void jacobi_expand(const float* __restrict__ x) {
    int base = blockIdx.x * 1024 + threadIdx.x;
    float t[4];
    #pragma unroll
    for (int e = 0; e < 4; ++e) t[e] = fast_tanh(x[base + e * 256]);
    #pragma unroll
    for (int e = 0; e < 4; ++e) {
        __half h[8];
        jacobi8_to_half(t[e], h);
        *reinterpret_cast<uint4*>(g_a + (size_t)(base + e * 256) * 8) =
            *reinterpret_cast<uint4*>(h);
    }
}

__global__ __launch_bounds__(256) void coef_convert(const float* __restrict__ coef) {
    int base = blockIdx.x * 1024 + threadIdx.x;
    #pragma unroll
    for (int e = 0; e < 4; ++e) {
        int idx = base + e * 256;
        float p[8];
        const float4* s = reinterpret_cast<const float4*>(coef + (size_t)idx * 8);
        *reinterpret_cast<float4*>(p)     = s[0];
        *reinterpret_cast<float4*>(p + 4) = s[1];
        __half h[8];
        #pragma unroll
        for (int d = 0; d < 8; ++d) h[d] = __float2half_rn(p[d]);
        *reinterpret_cast<uint4*>(g_b + (size_t)idx * 8) =
            *reinterpret_cast<uint4*>(h);
    }
}

// ---------------- phase 2: fp16 warp-MMA GEMM, high occupancy ---------------
// out[4096,512] = A[4096,4096] @ B[512,4096]^T, fp32 accumulate.
// BM=64, BN=128, BK=64, 128 threads (4 warps, warp tile 32x64).
// Stage = A(8KB) + B(16KB) = 24KB, 3 stages = 72KB/CTA -> 3 CTAs/SM.
// Grid = 256 CTAs -> most SMs hold 2 CTAs (4 warps/SMSP) for latency hiding.
#define BKH 64
#define A_BYTES 8192
#define STAGE_BYTES 24576
#define NSTAGE 3
#define SMEM_DYN (1024 + NSTAGE * STAGE_BYTES)

// swizzled offset inside a [rows][64 fp16] tile: 128B rows, 16B chunks
__device__ __forceinline__ uint32_t swoff(int row, int chunk) {
    return (uint32_t)(row * 128 + ((chunk ^ (row & 7)) * 16));
}

// load an nrows x 64-fp16 tile with cp.async (128 threads)
template<int NROWS>
__device__ __forceinline__ void load_tile(uint32_t sdst,
                                          const __half* gsrc, int tid) {
    #pragma unroll
    for (int t = 0; t < NROWS / 16; ++t) {       // NROWS*8 chunks / 128 thr
        int idx = t * 128 + tid;
        int row = idx >> 3, ch = idx & 7;
        cp16(sdst + swoff(row, ch),
             (const char*)(gsrc + (size_t)row * KK) + ch * 16);
    }
}

__global__ __launch_bounds__(128, 3)
void kan_gemm(float* __restrict__ out) {
    extern __shared__ char smraw[];
    uint32_t sbase = (smem_u32(smraw) + 1023) & ~1023u;

    const int tid  = threadIdx.x;
    const int lane = tid & 31;
    const int wid  = tid >> 5;          // 0..3
    const int wm   = wid >> 1;          // 0..1  (32-row slice)
    const int wn   = wid & 1;           // 0..1  (64-col slice)
    const int brow = blockIdx.y * 64;
    const int bcol = blockIdx.x * 128;

    const __half* A = g_a + (size_t)brow * KK;
    const __half* B = g_b + (size_t)bcol * KK;

    float acc[2][8][4];
    #pragma unroll
    for (int i = 0; i < 2; ++i)
        #pragma unroll
        for (int j = 0; j < 8; ++j)
            #pragma unroll
            for (int c = 0; c < 4; ++c) acc[i][j][c] = 0.0f;

    // ldmatrix per-lane row / chunk-half mapping
    const int ar  = lane & 15;                        // A row within m16 tile
    const int ac  = lane >> 4;                        // A k-chunk half (0/1)
    const int br0 = ((lane >> 4) << 3) + (lane & 7);  // B row within n16 pair
    const int bc  = (lane >> 3) & 1;                  // B k-chunk half (0/1)

    // prologue: stages 0,1
    #pragma unroll
    for (int t = 0; t < NSTAGE - 1; ++t) {
        uint32_t sb = sbase + t * STAGE_BYTES;
        int k0 = t * BKH;
        load_tile<64>(sb,            A + k0, tid);
        load_tile<128>(sb + A_BYTES, B + k0, tid);
        asm volatile("cp.async.commit_group;" ::: "memory");
    }

    const int NIT = KK / BKH;            // 64
    for (int kt = 0; kt < NIT; ++kt) {
        asm volatile("cp.async.wait_group %0;" :: "n"(NSTAGE - 2) : "memory");
        __syncthreads();

        // prefetch tile kt+2 into stage (kt+2)%3
        int nk = kt + NSTAGE - 1;
        if (nk < NIT) {
            uint32_t sb = sbase + (nk % NSTAGE) * STAGE_BYTES;
            int k0 = nk * BKH;
            load_tile<64>(sb,            A + k0, tid);
            load_tile<128>(sb + A_BYTES, B + k0, tid);
        }
        asm volatile("cp.async.commit_group;" ::: "memory");

        // compute from stage kt%3
        uint32_t sb = sbase + (kt % NSTAGE) * STAGE_BYTES;
        uint32_t aB = sb, bB = sb + A_BYTES;

        #pragma unroll
        for (int s = 0; s < 4; ++s) {            // 4 k16 steps in BK=64
            uint32_t a[2][4];
            #pragma unroll
            for (int mt = 0; mt < 2; ++mt)
                ldsm4(a[mt], aB + swoff(wm * 32 + mt * 16 + ar, s * 2 + ac));
            uint32_t b[4][4];
            #pragma unroll
            for (int p = 0; p < 4; ++p)
                ldsm4(b[p], bB + swoff(wn * 64 + p * 16 + br0, s * 2 + bc));
            #pragma unroll
            for (int mt = 0; mt < 2; ++mt)
                #pragma unroll
                for (int p = 0; p < 4; ++p) {
                    mma16816(acc[mt][2*p],   a[mt], b[p][0], b[p][1]);
                    mma16816(acc[mt][2*p+1], a[mt], b[p][2], b[p][3]);
                }
        }
        __syncthreads();
    }

    // epilogue: c-fragment layout -> float2 stores
    const int r0 = brow + wm * 32 + (lane >> 2);
    const int c0 = bcol + wn * 64 + (lane & 3) * 2;
    #pragma unroll
    for (int mt = 0; mt < 2; ++mt) {
        #pragma unroll
        for (int nt = 0; nt < 8; ++nt) {
            float* p = out + (size_t)(r0 + mt * 16) * NO + c0 + nt * 8;
            *reinterpret_cast<float2*>(p) =
                make_float2(acc[mt][nt][0], acc[mt][nt][1]);
            *reinterpret_cast<float2*>(p + 8 * NO) =
                make_float2(acc[mt][nt][2], acc[mt][nt][3]);
        }
    }
}

// ---------------- launcher ---------------------------------------------------
extern "C" void kernel_launch(void* const* d_in, const int* in_sizes, int n_in,
                              void* d_out, int out_size)
{
    const float* x    = (const float*)d_in[0];   // [4096, 512]
    const float* coef = (const float*)d_in[1];   // [512, 512, 8]
    float* out        = (float*)d_out;           // [4096, 512]

    cudaFuncSetAttribute(kan_gemm, cudaFuncAttributeMaxDynamicSharedMemorySize,
                         SMEM_DYN);

    jacobi_expand<<<(B_SZ * NI) / 1024, 256>>>(x);
    coef_convert<<<(NO * NI) / 1024, 256>>>(coef);

    dim3 grid(NO / 128, B_SZ / 64);              // (4, 64) = 256 CTAs
    kan_gemm<<<grid, 128, SMEM_DYN>>>(out);
}

// round 13
// speedup vs baseline: 1.2867x; 1.1139x over previous
#include <cuda_runtime.h>
#include <cuda_fp16.h>
#include <cstdint>

#define B_SZ 4096
#define NI   512
#define NO   512
#define KK   (NI*8)          // 4096

// ---------------- scratch (device globals; no allocation allowed) ----------
__device__ __half g_a[(size_t)B_SZ * KK];   // 32 MB
__device__ __half g_b[(size_t)NO * KK];     //  4 MB

// ---------------- helpers ---------------------------------------------------
__device__ __forceinline__ uint32_t smem_u32(const void* p) {
    uint32_t a;
    asm("{ .reg .u64 t; cvta.to.shared.u64 t, %1; cvt.u32.u64 %0, t; }"
        : "=r"(a) : "l"(p));
    return a;
}
__device__ __forceinline__ void cp16(uint32_t dst, const void* src) {
    asm volatile("cp.async.cg.shared.global [%0], [%1], 16;"
                 :: "r"(dst), "l"(src));
}
__device__ __forceinline__ void ldsm4(uint32_t* r, uint32_t addr) {
    asm volatile("ldmatrix.sync.aligned.m8n8.x4.shared.b16 {%0,%1,%2,%3}, [%4];"
                 : "=r"(r[0]), "=r"(r[1]), "=r"(r[2]), "=r"(r[3]) : "r"(addr));
}
__device__ __forceinline__ void mma16816(float* d, const uint32_t* a,
                                         uint32_t b0, uint32_t b1) {
    asm volatile(
        "mma.sync.aligned.m16n8k16.row.col.f32.f16.f16.f32 "
        "{%0,%1,%2,%3}, {%4,%5,%6,%7}, {%8,%9}, {%0,%1,%2,%3};"
        : "+f"(d[0]), "+f"(d[1]), "+f"(d[2]), "+f"(d[3])
        : "r"(a[0]), "r"(a[1]), "r"(a[2]), "r"(a[3]), "r"(b0), "r"(b1));
}

// fast tanh: rel err ~1e-6, far below fp16 quantization (2^-11)
__device__ __forceinline__ float fast_tanh(float x) {
    float xc = fminf(fmaxf(x, -9.0f), 9.0f);
    float e  = __expf(2.0f * xc);
    return 1.0f - __fdividef(2.0f, e + 1.0f);
}

__device__ __forceinline__ void jacobi8_to_half(float t, __half* h) {
    float p[8];
    p[0] = 1.0f;
    p[1] = 2.0f * t;
    p[2] = 1.875f      * t * p[1] - 0.75f       * p[0];
    p[3] = 1.8666667f  * t * p[2] - 0.8f        * p[1];
    p[4] = 1.875f      * t * p[3] - 0.8333333f  * p[2];
    p[5] = 1.8857143f  * t * p[4] - 0.85714287f * p[3];
    p[6] = 1.8958334f  * t * p[5] - 0.875f      * p[4];
    p[7] = 1.9047619f  * t * p[6] - 0.8888889f  * p[5];
    #pragma unroll
    for (int d = 0; d < 8; ++d) h[d] = __float2half_rn(p[d]);
}

// ---------------- phase 1: fused expand + coef convert ----------------------
// blocks [0, 2048): jacobi expand (4 elems/thread, stride-256)
// blocks [2048, 2304): coef convert (4 elems/thread, stride-256)
#define NBLK_A 2048
__global__ __launch_bounds__(256) void prep_kernel(const float* __restrict__ x,
                                                   const float* __restrict__ coef) {
    if (blockIdx.x < NBLK_A) {
        int base = blockIdx.x * 1024 + threadIdx.x;
        float t[4];
        #pragma unroll
        for (int e = 0; e < 4; ++e) t[e] = fast_tanh(x[base + e * 256]);
        #pragma unroll
        for (int e = 0; e < 4; ++e) {
            __half h[8];
            jacobi8_to_half(t[e], h);
            *reinterpret_cast<uint4*>(g_a + (size_t)(base + e * 256) * 8) =
                *reinterpret_cast<uint4*>(h);
        }
    } else {
        int base = (blockIdx.x - NBLK_A) * 1024 + threadIdx.x;
        #pragma unroll
        for (int e = 0; e < 4; ++e) {
            int idx = base + e * 256;
            float p[8];
            const float4* s = reinterpret_cast<const float4*>(coef + (size_t)idx * 8);
            *reinterpret_cast<float4*>(p)     = s[0];
            *reinterpret_cast<float4*>(p + 4) = s[1];
            __half h[8];
            #pragma unroll
            for (int d = 0; d < 8; ++d) h[d] = __float2half_rn(p[d]);
            *reinterpret_cast<uint4*>(g_b + (size_t)idx * 8) =
                *reinterpret_cast<uint4*>(h);
        }
    }
}

// ---------------- phase 2: fp16 warp-MMA GEMM, 64x64 warp tiles -------------
// out[4096,512] = A[4096,4096] @ B[512,4096]^T, fp32 accumulate.
// BM=BN=128, BK=128, 128 threads = 4 warps, warp tile 64x64 (2x2 grid).
// LDSM traffic/iter: 128KB (vs 192KB at 32x64) -> crossbar floor 1536 cyc.
// Stage = A(32KB)+B(32KB) = 64KB, 3 stages = 192KB.
#define BKH 128
#define SUB_BYTES 16384
#define STAGE_BYTES 65536
#define NSTAGE 3
#define SMEM_DYN (1024 + NSTAGE * STAGE_BYTES)

// swizzled offset inside a [rows][64 fp16] subtile: 128B rows, 16B chunks
__device__ __forceinline__ uint32_t swoff(int row, int chunk) {
    return (uint32_t)(row * 128 + ((chunk ^ (row & 7)) * 16));
}

// load one 128-row x 64-fp16 subtile (16KB) with cp.async, 128 threads
__device__ __forceinline__ void load_sub(uint32_t sdst,
                                         const __half* gsrc, int tid) {
    #pragma unroll
    for (int t = 0; t < 8; ++t) {
        int idx = t * 128 + tid;           // 1024 chunks of 16B
        int row = idx >> 3, ch = idx & 7;
        cp16(sdst + swoff(row, ch),
             (const char*)(gsrc + (size_t)row * KK) + ch * 16);
    }
}
__device__ __forceinline__ void load_stage(uint32_t sb, const __half* A,
                                           const __half* B, int k0, int tid) {
    load_sub(sb,                 A + k0,      tid);
    load_sub(sb + SUB_BYTES,     A + k0 + 64, tid);
    load_sub(sb + 2 * SUB_BYTES, B + k0,      tid);
    load_sub(sb + 3 * SUB_BYTES, B + k0 + 64, tid);
}

__global__ __launch_bounds__(128, 1)
void kan_gemm(float* __restrict__ out) {
    extern __shared__ char smraw[];
    uint32_t sbase = (smem_u32(smraw) + 1023) & ~1023u;

    const int tid  = threadIdx.x;
    const int lane = tid & 31;
    const int wid  = tid >> 5;          // 0..3
    const int wm   = wid >> 1;          // 0..1  (64-row slice)
    const int wn   = wid & 1;           // 0..1  (64-col slice)
    const int brow = blockIdx.y * 128;
    const int bcol = blockIdx.x * 128;

    const __half* A = g_a + (size_t)brow * KK;
    const __half* B = g_b + (size_t)bcol * KK;

    float acc[4][8][4];
    #pragma unroll
    for (int i = 0; i < 4; ++i)
        #pragma unroll
        for (int j = 0; j < 8; ++j)
            #pragma unroll
            for (int c = 0; c < 4; ++c) acc[i][j][c] = 0.0f;

    // ldmatrix per-lane row / chunk-half mapping
    const int ar  = lane & 15;                        // A row within m16 tile
    const int ac  = lane >> 4;                        // A k-chunk half (0/1)
    const int br0 = ((lane >> 4) << 3) + (lane & 7);  // B row within n16 pair
    const int bc  = (lane >> 3) & 1;                  // B k-chunk half (0/1)

    // prologue: stages 0,1
    #pragma unroll
    for (int t = 0; t < NSTAGE - 1; ++t) {
        load_stage(sbase + t * STAGE_BYTES, A, B, t * BKH, tid);
        asm volatile("cp.async.commit_group;" ::: "memory");
    }

    const int NIT = KK / BKH;            // 32
    for (int kt = 0; kt < NIT; ++kt) {
        asm volatile("cp.async.wait_group %0;" :: "n"(NSTAGE - 2) : "memory");
        __syncthreads();

        // prefetch tile kt+2 into stage (kt+2)%3
        int nk = kt + NSTAGE - 1;
        if (nk < NIT) {
            load_stage(sbase + (nk % NSTAGE) * STAGE_BYTES, A, B, nk * BKH, tid);
        }
        asm volatile("cp.async.commit_group;" ::: "memory");

        // compute from stage kt%3: two 64-col k-halves x 4 k16-steps
        uint32_t sb = sbase + (kt % NSTAGE) * STAGE_BYTES;
        #pragma unroll
        for (int h = 0; h < 2; ++h) {
            uint32_t aB = sb + h * SUB_BYTES;
            uint32_t bB = sb + (2 + h) * SUB_BYTES;
            #pragma unroll
            for (int s = 0; s < 4; ++s) {
                uint32_t a[4][4];
                #pragma unroll
                for (int mt = 0; mt < 4; ++mt)
                    ldsm4(a[mt], aB + swoff(wm * 64 + mt * 16 + ar, s * 2 + ac));
                uint32_t b[4][4];
                #pragma unroll
                for (int p = 0; p < 4; ++p)
                    ldsm4(b[p], bB + swoff(wn * 64 + p * 16 + br0, s * 2 + bc));
                #pragma unroll
                for (int mt = 0; mt < 4; ++mt)
                    #pragma unroll
                    for (int p = 0; p < 4; ++p) {
                        mma16816(acc[mt][2*p],   a[mt], b[p][0], b[p][1]);
                        mma16816(acc[mt][2*p+1], a[mt], b[p][2], b[p][3]);
                    }
            }
        }
        __syncthreads();
    }

    // epilogue: c-fragment layout -> float2 stores
    const int r0 = brow + wm * 64 + (lane >> 2);
    const int c0 = bcol + wn * 64 + (lane & 3) * 2;
    #pragma unroll
    for (int mt = 0; mt < 4; ++mt) {
        #pragma unroll
        for (int nt = 0; nt < 8; ++nt) {
            float* p = out + (size_t)(r0 + mt * 16) * NO + c0 + nt * 8;
            *reinterpret_cast<float2*>(p) =
                make_float2(acc[mt][nt][0], acc[mt][nt][1]);
            *reinterpret_cast<float2*>(p + 8 * NO) =
                make_float2(acc[mt][nt][2], acc[mt][nt][3]);
        }
    }
}

// ---------------- launcher ---------------------------------------------------
extern "C" void kernel_launch(void* const* d_in, const int* in_sizes, int n_in,
                              void* d_out, int out_size)
{
    const float* x    = (const float*)d_in[0];   // [4096, 512]
    const float* coef = (const float*)d_in[1];   // [512, 512, 8]
    float* out        = (float*)d_out;           // [4096, 512]

    cudaFuncSetAttribute(kan_gemm, cudaFuncAttributeMaxDynamicSharedMemorySize,
                         SMEM_DYN);

    prep_kernel<<<NBLK_A + (NO * NI) / 1024, 256>>>(x, coef);

    dim3 grid(NO / 128, B_SZ / 128);             // (4, 32)
    kan_gemm<<<grid, 128, SMEM_DYN>>>(out);
}